// round 14
// baseline (speedup 1.0000x reference)
#include <cuda_runtime.h>
#include <cstdint>

// ---------------------------------------------------------------------------
// ClinicalRLModel: embed-sum -> x@W_ih^T (tf32 mma) -> GRU(64) -> tail.
// RNG: JAX partitionable threefry, bits = out0 ^ out1, counter=(0, i).
// R14: R13 + f32x2 GRU matvec (isolated retry of the R7 idea, GEMM untouched).
// ---------------------------------------------------------------------------

#define B_SZ 128
#define T_SZ 64
#define C_SZ 24
#define EMB 128
#define HID 128
#define G3 384           // 3*HID
#define K2E 256          // 2*EMB

__device__ __align__(16) float g_x[B_SZ * T_SZ * K2E];      // (8192, 256)
__device__ __align__(16) float g_xproj[B_SZ * T_SZ * G3];   // (8192, 384)
__device__ __align__(16) float g_rnn[B_SZ * T_SZ * HID];    // (128, 64, 128)

typedef unsigned long long u64;

__device__ __forceinline__ void unpack2(u64 p, float& lo, float& hi) {
    asm("mov.b64 {%0, %1}, %2;" : "=f"(lo), "=f"(hi) : "l"(p));
}
__device__ __forceinline__ void ffma2(u64& d, u64 a, u64 b) {
    asm("fma.rn.f32x2 %0, %1, %2, %0;" : "+l"(d) : "l"(a), "l"(b));
}

// ---------------------------------------------------------------------------
// K1: embedding gather + sum over C, writes x = [e1 | e2]
// ---------------------------------------------------------------------------
__global__ void embed_kernel(const int* __restrict__ cond,
                             const int* __restrict__ proc,
                             const float* __restrict__ emb_c,
                             const float* __restrict__ emb_p) {
    int gw   = (blockIdx.x * blockDim.x + threadIdx.x) >> 5;
    int lane = threadIdx.x & 31;
    if (gw >= B_SZ * T_SZ * 2) return;
    int table = gw & 1;
    int bt    = gw >> 1;

    const int*   idx = (table ? proc : cond) + bt * C_SZ;
    const float* tab = table ? emb_p : emb_c;

    float4 acc = make_float4(0.f, 0.f, 0.f, 0.f);
#pragma unroll
    for (int j = 0; j < C_SZ; j++) {
        int r = __ldg(&idx[j]);
        float4 v = __ldg(((const float4*)(tab + (long)r * EMB)) + lane);
        acc.x += v.x; acc.y += v.y; acc.z += v.z; acc.w += v.w;
    }
    ((float4*)(g_x + (long)bt * K2E + table * EMB))[lane] = acc;
}

// ---------------------------------------------------------------------------
// K2: tf32 tensor-core GEMM. x_proj = x @ W_ih^T + b_ih  (unchanged)
// ---------------------------------------------------------------------------
#define GM 128
#define GN 64
#define GK 32
#define GKP (GK + 4)

__device__ __forceinline__ uint32_t tf32r(float x) {
    uint32_t y;
    asm("cvt.rna.tf32.f32 %0, %1;" : "=r"(y) : "f"(x));
    return y;
}

__device__ __forceinline__ void mma_tf32(float c[4], const uint32_t a[4], const uint32_t b[2]) {
    asm volatile(
        "mma.sync.aligned.m16n8k8.row.col.f32.tf32.tf32.f32 "
        "{%0,%1,%2,%3},{%4,%5,%6,%7},{%8,%9},{%0,%1,%2,%3};"
        : "+f"(c[0]), "+f"(c[1]), "+f"(c[2]), "+f"(c[3])
        : "r"(a[0]), "r"(a[1]), "r"(a[2]), "r"(a[3]),
          "r"(b[0]), "r"(b[1]));
}

__global__ __launch_bounds__(256) void xproj_gemm(const float* __restrict__ Wih,
                                                  const float* __restrict__ bih) {
    __shared__ __align__(16) uint32_t As[GM][GKP];
    __shared__ __align__(16) uint32_t Bs[GN][GKP];

    int tid = threadIdx.x;
    int warp = tid >> 5, lane = tid & 31;
    int wm = warp & 3;
    int wn = warp >> 2;
    int bm = blockIdx.x * GM;
    int bn = blockIdx.y * GN;

    int lr = lane >> 2;
    int lc = lane & 3;

    float c[2][4][4];
#pragma unroll
    for (int i = 0; i < 2; i++)
#pragma unroll
        for (int j = 0; j < 4; j++)
#pragma unroll
            for (int q = 0; q < 4; q++) c[i][j][q] = 0.f;

    float4 ra[4], rb[2];

#define LDG_A(k0)                                                         \
    {                                                                     \
        _Pragma("unroll") for (int i = 0; i < 4; i++) {                   \
            int idx = tid + i * 256;                                      \
            ra[i] = *(const float4*)(g_x + (long)(bm + (idx >> 3)) * K2E  \
                                     + (k0) + (idx & 7) * 4);             \
        }                                                                 \
    }
#define LDG_B(k0)                                                         \
    {                                                                     \
        _Pragma("unroll") for (int i = 0; i < 2; i++) {                   \
            int idx = tid + i * 256;                                      \
            rb[i] = *(const float4*)(Wih + (long)(bn + (idx >> 3)) * K2E  \
                                     + (k0) + (idx & 7) * 4);             \
        }                                                                 \
    }

    LDG_A(0);
    LDG_B(0);

    for (int s = 0; s < 8; s++) {
        __syncthreads();
#pragma unroll
        for (int i = 0; i < 4; i++) {
            int idx = tid + i * 256;
            uint32_t* d = &As[idx >> 3][(idx & 7) * 4];
            d[0] = tf32r(ra[i].x); d[1] = tf32r(ra[i].y);
            d[2] = tf32r(ra[i].z); d[3] = tf32r(ra[i].w);
        }
#pragma unroll
        for (int i = 0; i < 2; i++) {
            int idx = tid + i * 256;
            uint32_t* d = &Bs[idx >> 3][(idx & 7) * 4];
            d[0] = tf32r(rb[i].x); d[1] = tf32r(rb[i].y);
            d[2] = tf32r(rb[i].z); d[3] = tf32r(rb[i].w);
        }
        __syncthreads();
        if (s < 7) { LDG_A((s + 1) * GK); LDG_B((s + 1) * GK); }

#pragma unroll
        for (int ks = 0; ks < 4; ks++) {
            int kk = ks * 8;
            uint32_t af[2][4], bf[4][2];
#pragma unroll
            for (int im = 0; im < 2; im++) {
                int r = wm * 32 + im * 16;
                af[im][0] = As[r + lr][kk + lc];
                af[im][1] = As[r + lr + 8][kk + lc];
                af[im][2] = As[r + lr][kk + lc + 4];
                af[im][3] = As[r + lr + 8][kk + lc + 4];
            }
#pragma unroll
            for (int in_ = 0; in_ < 4; in_++) {
                int cn = wn * 32 + in_ * 8 + lr;
                bf[in_][0] = Bs[cn][kk + lc];
                bf[in_][1] = Bs[cn][kk + lc + 4];
            }
#pragma unroll
            for (int im = 0; im < 2; im++)
#pragma unroll
                for (int in_ = 0; in_ < 4; in_++)
                    mma_tf32(c[im][in_], af[im], bf[in_]);
        }
    }

#pragma unroll
    for (int im = 0; im < 2; im++) {
        int m0 = bm + wm * 32 + im * 16 + lr;
#pragma unroll
        for (int in_ = 0; in_ < 4; in_++) {
            int n = bn + wn * 32 + in_ * 8 + 2 * lc;
            float b0 = bih[n], b1 = bih[n + 1];
            float* d0 = g_xproj + (long)m0 * G3 + n;
            d0[0] = c[im][in_][0] + b0;
            d0[1] = c[im][in_][1] + b1;
            float* d1 = g_xproj + (long)(m0 + 8) * G3 + n;
            d1[0] = c[im][in_][2] + b0;
            d1[1] = c[im][in_][3] + b1;
        }
    }
}

// ---------------------------------------------------------------------------
// K3: GRU with f32x2 matvec. one block per batch row; 384 threads.
// W_hh register-resident as 64 u64 pairs; h read as LDS.64 pairs.
// Fast MUFU activations (R13).
// ---------------------------------------------------------------------------
__device__ __forceinline__ float fast_sigmoid(float x) {
    return __fdividef(1.f, 1.f + __expf(-x));
}

__global__ __launch_bounds__(G3) void gru_kernel(const float* __restrict__ Whh,
                                                 const float* __restrict__ bhh) {
    int b = blockIdx.x;
    int g = threadIdx.x;      // 0..383
    __shared__ __align__(16) float h_sh[HID];
    __shared__ float srz[2 * HID];
    __shared__ float sxn[HID];
    __shared__ float shn[HID];

    u64 w2[64];
    const u64* Wrow = (const u64*)(Whh + (long)g * HID);
#pragma unroll
    for (int k = 0; k < 64; k++) w2[k] = Wrow[k];
    float bb = bhh[g];
    if (g < HID) h_sh[g] = 0.f;
    __syncthreads();

    const float* xp_base = g_xproj + (long)b * T_SZ * G3;
    float* rnn_base = g_rnn + (long)b * T_SZ * HID;

    for (int t = 0; t < T_SZ; t++) {
        float xp = xp_base[t * G3 + g];
        const u64* h2 = (const u64*)h_sh;
        u64 accA = 0ull, accB = 0ull;
#pragma unroll
        for (int k = 0; k < 64; k += 2) {
            ffma2(accA, w2[k], h2[k]);
            ffma2(accB, w2[k + 1], h2[k + 1]);
        }
        float aLo, aHi, bLo, bHi;
        unpack2(accA, aLo, aHi);
        unpack2(accB, bLo, bHi);
        float acc = bb + ((aLo + aHi) + (bLo + bHi));
        if (g < 2 * HID) {
            srz[g] = xp + acc;
        } else {
            sxn[g - 2 * HID] = xp;
            shn[g - 2 * HID] = acc;
        }
        __syncthreads();
        if (g < HID) {
            float r = fast_sigmoid(srz[g]);
            float z = fast_sigmoid(srz[HID + g]);
            float xn = sxn[g] + r * shn[g];
            float n = 2.f * fast_sigmoid(2.f * xn) - 1.f;   // tanh(xn)
            float hn = (1.f - z) * n + z * h_sh[g];
            h_sh[g] = hn;
            rnn_base[t * HID + g] = hn;
        }
        __syncthreads();
    }
}

// ---------------------------------------------------------------------------
// threefry2x32, JAX-exact
// ---------------------------------------------------------------------------
__device__ __forceinline__ uint32_t rotl32(uint32_t v, int d) {
    return (v << d) | (v >> (32 - d));
}
__device__ void threefry2x32(uint32_t k0, uint32_t k1, uint32_t& x0, uint32_t& x1) {
    const uint32_t ks0 = k0, ks1 = k1, ks2 = k0 ^ k1 ^ 0x1BD11BDAu;
    const int r0[4] = {13, 15, 26, 6};
    const int r1[4] = {17, 29, 16, 24};
    x0 += ks0; x1 += ks1;
#pragma unroll
    for (int i = 0; i < 4; i++) { x0 += x1; x1 = rotl32(x1, r0[i]); x1 ^= x0; }
    x0 += ks1; x1 += ks2 + 1u;
#pragma unroll
    for (int i = 0; i < 4; i++) { x0 += x1; x1 = rotl32(x1, r1[i]); x1 ^= x0; }
    x0 += ks2; x1 += ks0 + 2u;
#pragma unroll
    for (int i = 0; i < 4; i++) { x0 += x1; x1 = rotl32(x1, r0[i]); x1 ^= x0; }
    x0 += ks0; x1 += ks1 + 3u;
#pragma unroll
    for (int i = 0; i < 4; i++) { x0 += x1; x1 = rotl32(x1, r1[i]); x1 ^= x0; }
    x0 += ks1; x1 += ks2 + 4u;
#pragma unroll
    for (int i = 0; i < 4; i++) { x0 += x1; x1 = rotl32(x1, r0[i]); x1 ^= x0; }
    x0 += ks2; x1 += ks0 + 5u;
}

__device__ __forceinline__ uint32_t jax_bits_partitionable(uint32_t i) {
    uint32_t x0 = 0u, x1 = i;
    threefry2x32(0u, 42u, x0, x1);          // key(42) -> (0, 42)
    return x0 ^ x1;
}

// ---------------------------------------------------------------------------
// K4: warp-parallel matvecs, f32x2 loads/FMA, 512 threads = 16 warps.
// ---------------------------------------------------------------------------
__device__ __forceinline__ float warp_reduce_sum(float v) {
    v += __shfl_down_sync(0xffffffffu, v, 16);
    v += __shfl_down_sync(0xffffffffu, v, 8);
    v += __shfl_down_sync(0xffffffffu, v, 4);
    v += __shfl_down_sync(0xffffffffu, v, 2);
    v += __shfl_down_sync(0xffffffffu, v, 1);
    return v;
}

__global__ __launch_bounds__(512) void tail_kernel(const float* __restrict__ Wp1,
                                                   const float* __restrict__ bp1,
                                                   const float* __restrict__ Wp2,
                                                   const float* __restrict__ bp2,
                                                   const float* __restrict__ Wf,
                                                   const float* __restrict__ bf,
                                                   const float* __restrict__ Wo,
                                                   const float* __restrict__ bo,
                                                   float* __restrict__ out) {
    int b = blockIdx.x;
    int tid = threadIdx.x;
    int w = tid >> 5;          // 0..15
    int l = tid & 31;

    __shared__ __align__(16) float cat[2 * HID];
    __shared__ __align__(16) float a1[64];
    __shared__ __align__(16) float fused[HID];
    __shared__ float lgt[10];
    __shared__ int s_act;

    const float* rnn_b = g_rnn + (long)b * T_SZ * HID;
    if (tid < HID) cat[tid] = rnn_b[63 * HID + tid];
    __syncthreads();

    const u64* catp = (const u64*)cat;

    {
        int j = w * 4;
#pragma unroll
        for (int jj = 0; jj < 4; jj++, j++) {
            const u64* rowp = (const u64*)(Wp1 + j * HID);
            u64 s2 = 0ull;
            ffma2(s2, rowp[l], catp[l]);
            ffma2(s2, rowp[l + 32], catp[l + 32]);
            float slo, shi;
            unpack2(s2, slo, shi);
            float s = warp_reduce_sum(slo + shi);
            if (l == 0) a1[j] = tanhf(s + bp1[j]);
        }
    }
    __syncthreads();

    if (w < 10) {
        const u64* a1p = (const u64*)a1;
        const u64* rowp = (const u64*)(Wp2 + w * 64);
        u64 s2 = 0ull;
        ffma2(s2, rowp[l], a1p[l]);
        float slo, shi;
        unpack2(s2, slo, shi);
        float s = warp_reduce_sum(slo + shi);
        if (l == 0) lgt[w] = s + bp2[w];
    }
    __syncthreads();

    if (tid < 10) {
        uint32_t i = (uint32_t)(b * 630 + 620 + tid);
        uint32_t bits = jax_bits_partitionable(i);
        float u = __uint_as_float((bits >> 9) | 0x3f800000u) - 1.0f;
        u = fmaxf(u, 1.1754943508222875e-38f);
        lgt[tid] += -logf(-logf(u));
    }
    __syncthreads();
    if (tid == 0) {
        int best = 0;
        float bv = lgt[0];
#pragma unroll
        for (int a = 1; a < 10; a++)
            if (lgt[a] > bv) { bv = lgt[a]; best = a; }
        s_act = best;   // t=63: history window [53,63), clip keeps [0,9]
    }
    __syncthreads();

    if (tid < HID) cat[HID + tid] = rnn_b[(53 + s_act) * HID + tid];
    __syncthreads();

    {
        int j = w * 8;
#pragma unroll
        for (int jj = 0; jj < 8; jj++, j++) {
            const u64* rowp = (const u64*)(Wf + j * 2 * HID);
            u64 s2 = 0ull;
#pragma unroll
            for (int q = 0; q < 4; q++) ffma2(s2, rowp[l + 32 * q], catp[l + 32 * q]);
            float slo, shi;
            unpack2(s2, slo, shi);
            float s = warp_reduce_sum(slo + shi);
            if (l == 0) fused[j] = fmaxf(s + bf[j], 0.f);
        }
    }
    __syncthreads();

    const u64* fup = (const u64*)fused;

    {
        int j = w * 13;
#pragma unroll
        for (int jj = 0; jj < 13; jj++, j++) {
            if (j < 200) {
                const u64* rowp = (const u64*)(Wo + j * HID);
                u64 s2 = 0ull;
                ffma2(s2, rowp[l], fup[l]);
                ffma2(s2, rowp[l + 32], fup[l + 32]);
                float slo, shi;
                unpack2(s2, slo, shi);
                float s = warp_reduce_sum(slo + shi);
                if (l == 0) out[b * 200 + j] = s + bo[j];
            }
        }
    }
}

// ---------------------------------------------------------------------------
extern "C" void kernel_launch(void* const* d_in, const int* in_sizes, int n_in,
                              void* d_out, int out_size) {
    const void* p_cond = 0; const void* p_proc = 0;
    const void* p_embc = 0; const void* p_embp = 0;
    const void* p_wih = 0;  const void* p_whh = 0;
    const void* p_bih = 0;  const void* p_bhh = 0;
    const void* p_wp1 = 0;  const void* p_bp1 = 0;
    const void* p_wp2 = 0;  const void* p_bp2 = 0;
    const void* p_wf = 0;   const void* p_bf = 0;
    const void* p_wo = 0;   const void* p_bo = 0;

    for (int i = 0; i < n_in; i++) {
        int s = in_sizes[i];
        const void* p = d_in[i];
        switch (s) {
            case 196608: if (!p_cond) p_cond = p; else p_proc = p; break;
            case 640128: if (!p_embc) p_embc = p; else p_embp = p; break;
            case  98304: p_wih = p; break;
            case  49152: p_whh = p; break;
            case    384: if (!p_bih) p_bih = p; else p_bhh = p; break;
            case   8192: p_wp1 = p; break;
            case     64: p_bp1 = p; break;
            case    640: p_wp2 = p; break;
            case     10: p_bp2 = p; break;
            case  32768: p_wf = p; break;
            case    128: p_bf = p; break;
            case  25600: p_wo = p; break;
            case    200: p_bo = p; break;
            default: break;
        }
    }

    float* out = (float*)d_out;

    embed_kernel<<<2048, 256>>>((const int*)p_cond, (const int*)p_proc,
                                (const float*)p_embc, (const float*)p_embp);

    dim3 g2(B_SZ * T_SZ / GM, G3 / GN);     // (64, 6)
    xproj_gemm<<<g2, 256>>>((const float*)p_wih, (const float*)p_bih);

    gru_kernel<<<B_SZ, G3>>>((const float*)p_whh, (const float*)p_bhh);

    tail_kernel<<<B_SZ, 512>>>((const float*)p_wp1, (const float*)p_bp1,
                               (const float*)p_wp2, (const float*)p_bp2,
                               (const float*)p_wf,  (const float*)p_bf,
                               (const float*)p_wo,  (const float*)p_bo, out);
}

// round 15
// speedup vs baseline: 1.0909x; 1.0909x over previous
#include <cuda_runtime.h>
#include <cstdint>

// ---------------------------------------------------------------------------
// ClinicalRLModel: embed-sum -> x@W_ih^T (tf32 mma) -> GRU(64) -> tail.
// RNG: JAX partitionable threefry, bits = out0 ^ out1, counter=(0, i).
// R15: R13 base (f32x2 GRU condemned); tail -> 1024 thr + MUFU log/tanh.
// ---------------------------------------------------------------------------

#define B_SZ 128
#define T_SZ 64
#define C_SZ 24
#define EMB 128
#define HID 128
#define G3 384           // 3*HID
#define K2E 256          // 2*EMB

__device__ __align__(16) float g_x[B_SZ * T_SZ * K2E];      // (8192, 256)
__device__ __align__(16) float g_xproj[B_SZ * T_SZ * G3];   // (8192, 384)
__device__ __align__(16) float g_rnn[B_SZ * T_SZ * HID];    // (128, 64, 128)

typedef unsigned long long u64;

__device__ __forceinline__ void unpack2(u64 p, float& lo, float& hi) {
    asm("mov.b64 {%0, %1}, %2;" : "=f"(lo), "=f"(hi) : "l"(p));
}
__device__ __forceinline__ void ffma2(u64& d, u64 a, u64 b) {
    asm("fma.rn.f32x2 %0, %1, %2, %0;" : "+l"(d) : "l"(a), "l"(b));
}

// ---------------------------------------------------------------------------
// K1: embedding gather + sum over C, writes x = [e1 | e2]
// ---------------------------------------------------------------------------
__global__ void embed_kernel(const int* __restrict__ cond,
                             const int* __restrict__ proc,
                             const float* __restrict__ emb_c,
                             const float* __restrict__ emb_p) {
    int gw   = (blockIdx.x * blockDim.x + threadIdx.x) >> 5;
    int lane = threadIdx.x & 31;
    if (gw >= B_SZ * T_SZ * 2) return;
    int table = gw & 1;
    int bt    = gw >> 1;

    const int*   idx = (table ? proc : cond) + bt * C_SZ;
    const float* tab = table ? emb_p : emb_c;

    float4 acc = make_float4(0.f, 0.f, 0.f, 0.f);
#pragma unroll
    for (int j = 0; j < C_SZ; j++) {
        int r = __ldg(&idx[j]);
        float4 v = __ldg(((const float4*)(tab + (long)r * EMB)) + lane);
        acc.x += v.x; acc.y += v.y; acc.z += v.z; acc.w += v.w;
    }
    ((float4*)(g_x + (long)bt * K2E + table * EMB))[lane] = acc;
}

// ---------------------------------------------------------------------------
// K2: tf32 tensor-core GEMM. x_proj = x @ W_ih^T + b_ih  (unchanged)
// ---------------------------------------------------------------------------
#define GM 128
#define GN 64
#define GK 32
#define GKP (GK + 4)

__device__ __forceinline__ uint32_t tf32r(float x) {
    uint32_t y;
    asm("cvt.rna.tf32.f32 %0, %1;" : "=r"(y) : "f"(x));
    return y;
}

__device__ __forceinline__ void mma_tf32(float c[4], const uint32_t a[4], const uint32_t b[2]) {
    asm volatile(
        "mma.sync.aligned.m16n8k8.row.col.f32.tf32.tf32.f32 "
        "{%0,%1,%2,%3},{%4,%5,%6,%7},{%8,%9},{%0,%1,%2,%3};"
        : "+f"(c[0]), "+f"(c[1]), "+f"(c[2]), "+f"(c[3])
        : "r"(a[0]), "r"(a[1]), "r"(a[2]), "r"(a[3]),
          "r"(b[0]), "r"(b[1]));
}

__global__ __launch_bounds__(256) void xproj_gemm(const float* __restrict__ Wih,
                                                  const float* __restrict__ bih) {
    __shared__ __align__(16) uint32_t As[GM][GKP];
    __shared__ __align__(16) uint32_t Bs[GN][GKP];

    int tid = threadIdx.x;
    int warp = tid >> 5, lane = tid & 31;
    int wm = warp & 3;
    int wn = warp >> 2;
    int bm = blockIdx.x * GM;
    int bn = blockIdx.y * GN;

    int lr = lane >> 2;
    int lc = lane & 3;

    float c[2][4][4];
#pragma unroll
    for (int i = 0; i < 2; i++)
#pragma unroll
        for (int j = 0; j < 4; j++)
#pragma unroll
            for (int q = 0; q < 4; q++) c[i][j][q] = 0.f;

    float4 ra[4], rb[2];

#define LDG_A(k0)                                                         \
    {                                                                     \
        _Pragma("unroll") for (int i = 0; i < 4; i++) {                   \
            int idx = tid + i * 256;                                      \
            ra[i] = *(const float4*)(g_x + (long)(bm + (idx >> 3)) * K2E  \
                                     + (k0) + (idx & 7) * 4);             \
        }                                                                 \
    }
#define LDG_B(k0)                                                         \
    {                                                                     \
        _Pragma("unroll") for (int i = 0; i < 2; i++) {                   \
            int idx = tid + i * 256;                                      \
            rb[i] = *(const float4*)(Wih + (long)(bn + (idx >> 3)) * K2E  \
                                     + (k0) + (idx & 7) * 4);             \
        }                                                                 \
    }

    LDG_A(0);
    LDG_B(0);

    for (int s = 0; s < 8; s++) {
        __syncthreads();
#pragma unroll
        for (int i = 0; i < 4; i++) {
            int idx = tid + i * 256;
            uint32_t* d = &As[idx >> 3][(idx & 7) * 4];
            d[0] = tf32r(ra[i].x); d[1] = tf32r(ra[i].y);
            d[2] = tf32r(ra[i].z); d[3] = tf32r(ra[i].w);
        }
#pragma unroll
        for (int i = 0; i < 2; i++) {
            int idx = tid + i * 256;
            uint32_t* d = &Bs[idx >> 3][(idx & 7) * 4];
            d[0] = tf32r(rb[i].x); d[1] = tf32r(rb[i].y);
            d[2] = tf32r(rb[i].z); d[3] = tf32r(rb[i].w);
        }
        __syncthreads();
        if (s < 7) { LDG_A((s + 1) * GK); LDG_B((s + 1) * GK); }

#pragma unroll
        for (int ks = 0; ks < 4; ks++) {
            int kk = ks * 8;
            uint32_t af[2][4], bf[4][2];
#pragma unroll
            for (int im = 0; im < 2; im++) {
                int r = wm * 32 + im * 16;
                af[im][0] = As[r + lr][kk + lc];
                af[im][1] = As[r + lr + 8][kk + lc];
                af[im][2] = As[r + lr][kk + lc + 4];
                af[im][3] = As[r + lr + 8][kk + lc + 4];
            }
#pragma unroll
            for (int in_ = 0; in_ < 4; in_++) {
                int cn = wn * 32 + in_ * 8 + lr;
                bf[in_][0] = Bs[cn][kk + lc];
                bf[in_][1] = Bs[cn][kk + lc + 4];
            }
#pragma unroll
            for (int im = 0; im < 2; im++)
#pragma unroll
                for (int in_ = 0; in_ < 4; in_++)
                    mma_tf32(c[im][in_], af[im], bf[in_]);
        }
    }

#pragma unroll
    for (int im = 0; im < 2; im++) {
        int m0 = bm + wm * 32 + im * 16 + lr;
#pragma unroll
        for (int in_ = 0; in_ < 4; in_++) {
            int n = bn + wn * 32 + in_ * 8 + 2 * lc;
            float b0 = bih[n], b1 = bih[n + 1];
            float* d0 = g_xproj + (long)m0 * G3 + n;
            d0[0] = c[im][in_][0] + b0;
            d0[1] = c[im][in_][1] + b1;
            float* d1 = g_xproj + (long)(m0 + 8) * G3 + n;
            d1[0] = c[im][in_][2] + b0;
            d1[1] = c[im][in_][3] + b1;
        }
    }
}

// ---------------------------------------------------------------------------
// K3: GRU (R13: float4 h loads, serial acc, MUFU activations). UNCHANGED.
// ---------------------------------------------------------------------------
__device__ __forceinline__ float fast_sigmoid(float x) {
    return __fdividef(1.f, 1.f + __expf(-x));
}

__global__ __launch_bounds__(G3) void gru_kernel(const float* __restrict__ Whh,
                                                 const float* __restrict__ bhh) {
    int b = blockIdx.x;
    int g = threadIdx.x;      // 0..383
    __shared__ __align__(16) float h_sh[HID];
    __shared__ float srz[2 * HID];
    __shared__ float sxn[HID];
    __shared__ float shn[HID];

    float w[HID];
#pragma unroll
    for (int k = 0; k < HID; k += 4) {
        float4 v = *(const float4*)(Whh + (long)g * HID + k);
        w[k] = v.x; w[k + 1] = v.y; w[k + 2] = v.z; w[k + 3] = v.w;
    }
    float bb = bhh[g];
    if (g < HID) h_sh[g] = 0.f;
    __syncthreads();

    const float* xp_base = g_xproj + (long)b * T_SZ * G3;
    float* rnn_base = g_rnn + (long)b * T_SZ * HID;

    for (int t = 0; t < T_SZ; t++) {
        float xp = xp_base[t * G3 + g];
        float acc = bb;
#pragma unroll
        for (int k = 0; k < HID; k += 4) {
            float4 hv = *(const float4*)&h_sh[k];
            acc += w[k] * hv.x;
            acc += w[k + 1] * hv.y;
            acc += w[k + 2] * hv.z;
            acc += w[k + 3] * hv.w;
        }
        if (g < 2 * HID) {
            srz[g] = xp + acc;
        } else {
            sxn[g - 2 * HID] = xp;
            shn[g - 2 * HID] = acc;
        }
        __syncthreads();
        if (g < HID) {
            float r = fast_sigmoid(srz[g]);
            float z = fast_sigmoid(srz[HID + g]);
            float xn = sxn[g] + r * shn[g];
            float n = 2.f * fast_sigmoid(2.f * xn) - 1.f;   // tanh(xn)
            float hn = (1.f - z) * n + z * h_sh[g];
            h_sh[g] = hn;
            rnn_base[t * HID + g] = hn;
        }
        __syncthreads();
    }
}

// ---------------------------------------------------------------------------
// threefry2x32, JAX-exact
// ---------------------------------------------------------------------------
__device__ __forceinline__ uint32_t rotl32(uint32_t v, int d) {
    return (v << d) | (v >> (32 - d));
}
__device__ void threefry2x32(uint32_t k0, uint32_t k1, uint32_t& x0, uint32_t& x1) {
    const uint32_t ks0 = k0, ks1 = k1, ks2 = k0 ^ k1 ^ 0x1BD11BDAu;
    const int r0[4] = {13, 15, 26, 6};
    const int r1[4] = {17, 29, 16, 24};
    x0 += ks0; x1 += ks1;
#pragma unroll
    for (int i = 0; i < 4; i++) { x0 += x1; x1 = rotl32(x1, r0[i]); x1 ^= x0; }
    x0 += ks1; x1 += ks2 + 1u;
#pragma unroll
    for (int i = 0; i < 4; i++) { x0 += x1; x1 = rotl32(x1, r1[i]); x1 ^= x0; }
    x0 += ks2; x1 += ks0 + 2u;
#pragma unroll
    for (int i = 0; i < 4; i++) { x0 += x1; x1 = rotl32(x1, r0[i]); x1 ^= x0; }
    x0 += ks0; x1 += ks1 + 3u;
#pragma unroll
    for (int i = 0; i < 4; i++) { x0 += x1; x1 = rotl32(x1, r1[i]); x1 ^= x0; }
    x0 += ks1; x1 += ks2 + 4u;
#pragma unroll
    for (int i = 0; i < 4; i++) { x0 += x1; x1 = rotl32(x1, r0[i]); x1 ^= x0; }
    x0 += ks2; x1 += ks0 + 5u;
}

__device__ __forceinline__ uint32_t jax_bits_partitionable(uint32_t i) {
    uint32_t x0 = 0u, x1 = i;
    threefry2x32(0u, 42u, x0, x1);          // key(42) -> (0, 42)
    return x0 ^ x1;
}

// ---------------------------------------------------------------------------
// K4 v5: warp-parallel matvecs, 1024 threads = 32 warps; MUFU log/tanh.
// ---------------------------------------------------------------------------
__device__ __forceinline__ float warp_reduce_sum(float v) {
    v += __shfl_down_sync(0xffffffffu, v, 16);
    v += __shfl_down_sync(0xffffffffu, v, 8);
    v += __shfl_down_sync(0xffffffffu, v, 4);
    v += __shfl_down_sync(0xffffffffu, v, 2);
    v += __shfl_down_sync(0xffffffffu, v, 1);
    return v;
}

__global__ __launch_bounds__(1024) void tail_kernel(const float* __restrict__ Wp1,
                                                    const float* __restrict__ bp1,
                                                    const float* __restrict__ Wp2,
                                                    const float* __restrict__ bp2,
                                                    const float* __restrict__ Wf,
                                                    const float* __restrict__ bf,
                                                    const float* __restrict__ Wo,
                                                    const float* __restrict__ bo,
                                                    float* __restrict__ out) {
    int b = blockIdx.x;
    int tid = threadIdx.x;
    int w = tid >> 5;          // 0..31
    int l = tid & 31;

    __shared__ __align__(16) float cat[2 * HID];
    __shared__ __align__(16) float a1[64];
    __shared__ __align__(16) float fused[HID];
    __shared__ float lgt[10];
    __shared__ int s_act;

    const float* rnn_b = g_rnn + (long)b * T_SZ * HID;
    if (tid < HID) cat[tid] = rnn_b[63 * HID + tid];
    __syncthreads();

    const u64* catp = (const u64*)cat;

    // a1[j] = tanh(Wp1[j,:] . obs + bp1[j]) : 64 outputs, 2 per warp
    {
        int j = w * 2;
#pragma unroll
        for (int jj = 0; jj < 2; jj++, j++) {
            const u64* rowp = (const u64*)(Wp1 + j * HID);
            u64 s2 = 0ull;
            ffma2(s2, rowp[l], catp[l]);
            ffma2(s2, rowp[l + 32], catp[l + 32]);
            float slo, shi;
            unpack2(s2, slo, shi);
            float s = warp_reduce_sum(slo + shi);
            if (l == 0) {
                float x = s + bp1[j];
                a1[j] = 2.f * fast_sigmoid(2.f * x) - 1.f;   // tanh
            }
        }
    }
    __syncthreads();

    // logits: warps 0..9, one each (K=64)
    if (w < 10) {
        const u64* a1p = (const u64*)a1;
        const u64* rowp = (const u64*)(Wp2 + w * 64);
        u64 s2 = 0ull;
        ffma2(s2, rowp[l], a1p[l]);
        float slo, shi;
        unpack2(s2, slo, shi);
        float s = warp_reduce_sum(slo + shi);
        if (l == 0) lgt[w] = s + bp2[w];
    }
    __syncthreads();

    // gumbel noise + argmax (first-max-wins); MUFU log
    if (tid < 10) {
        uint32_t i = (uint32_t)(b * 630 + 620 + tid);
        uint32_t bits = jax_bits_partitionable(i);
        float u = __uint_as_float((bits >> 9) | 0x3f800000u) - 1.0f;
        u = fmaxf(u, 1.1754943508222875e-38f);
        lgt[tid] += -__logf(-__logf(u));
    }
    __syncthreads();
    if (tid == 0) {
        int best = 0;
        float bv = lgt[0];
#pragma unroll
        for (int a = 1; a < 10; a++)
            if (lgt[a] > bv) { bv = lgt[a]; best = a; }
        s_act = best;   // t=63: history window [53,63), clip keeps [0,9]
    }
    __syncthreads();

    if (tid < HID) cat[HID + tid] = rnn_b[(53 + s_act) * HID + tid];
    __syncthreads();

    // fused[j] = relu(Wf[j,:] . cat + bf[j]) : 128 outputs, 4 per warp
    {
        int j = w * 4;
#pragma unroll
        for (int jj = 0; jj < 4; jj++, j++) {
            const u64* rowp = (const u64*)(Wf + j * 2 * HID);
            u64 s2 = 0ull;
#pragma unroll
            for (int q = 0; q < 4; q++) ffma2(s2, rowp[l + 32 * q], catp[l + 32 * q]);
            float slo, shi;
            unpack2(s2, slo, shi);
            float s = warp_reduce_sum(slo + shi);
            if (l == 0) fused[j] = fmaxf(s + bf[j], 0.f);
        }
    }
    __syncthreads();

    const u64* fup = (const u64*)fused;

    // out[j] = Wo[j,:] . fused + bo[j] : 200 outputs, 7 per warp (guarded)
    {
        int j = w * 7;
#pragma unroll
        for (int jj = 0; jj < 7; jj++, j++) {
            if (j < 200) {
                const u64* rowp = (const u64*)(Wo + j * HID);
                u64 s2 = 0ull;
                ffma2(s2, rowp[l], fup[l]);
                ffma2(s2, rowp[l + 32], fup[l + 32]);
                float slo, shi;
                unpack2(s2, slo, shi);
                float s = warp_reduce_sum(slo + shi);
                if (l == 0) out[b * 200 + j] = s + bo[j];
            }
        }
    }
}

// ---------------------------------------------------------------------------
extern "C" void kernel_launch(void* const* d_in, const int* in_sizes, int n_in,
                              void* d_out, int out_size) {
    const void* p_cond = 0; const void* p_proc = 0;
    const void* p_embc = 0; const void* p_embp = 0;
    const void* p_wih = 0;  const void* p_whh = 0;
    const void* p_bih = 0;  const void* p_bhh = 0;
    const void* p_wp1 = 0;  const void* p_bp1 = 0;
    const void* p_wp2 = 0;  const void* p_bp2 = 0;
    const void* p_wf = 0;   const void* p_bf = 0;
    const void* p_wo = 0;   const void* p_bo = 0;

    for (int i = 0; i < n_in; i++) {
        int s = in_sizes[i];
        const void* p = d_in[i];
        switch (s) {
            case 196608: if (!p_cond) p_cond = p; else p_proc = p; break;
            case 640128: if (!p_embc) p_embc = p; else p_embp = p; break;
            case  98304: p_wih = p; break;
            case  49152: p_whh = p; break;
            case    384: if (!p_bih) p_bih = p; else p_bhh = p; break;
            case   8192: p_wp1 = p; break;
            case     64: p_bp1 = p; break;
            case    640: p_wp2 = p; break;
            case     10: p_bp2 = p; break;
            case  32768: p_wf = p; break;
            case    128: p_bf = p; break;
            case  25600: p_wo = p; break;
            case    200: p_bo = p; break;
            default: break;
        }
    }

    float* out = (float*)d_out;

    embed_kernel<<<2048, 256>>>((const int*)p_cond, (const int*)p_proc,
                                (const float*)p_embc, (const float*)p_embp);

    dim3 g2(B_SZ * T_SZ / GM, G3 / GN);     // (64, 6)
    xproj_gemm<<<g2, 256>>>((const float*)p_wih, (const float*)p_bih);

    gru_kernel<<<B_SZ, G3>>>((const float*)p_whh, (const float*)p_bhh);

    tail_kernel<<<B_SZ, 1024>>>((const float*)p_wp1, (const float*)p_bp1,
                                (const float*)p_wp2, (const float*)p_bp2,
                                (const float*)p_wf,  (const float*)p_bf,
                                (const float*)p_wo,  (const float*)p_bo, out);
}